// round 1
// baseline (speedup 1.0000x reference)
#include <cuda_runtime.h>
#include <math.h>

// Problem dims
#define H_    128
#define B_    16
#define L_    4096
#define SN    64      // SSM state size N
#define CHK   128     // chunk length
#define NCH   32      // number of chunks (L/CHK)
#define COLS_ 512     // B_*NCH
#define KC_   256     // GEMM-C K dim (2*SN + CHK)

// ---------------- device scratch (static globals; no allocation) ----------------
static __device__ __align__(16) float g_pow[H_ * 129 * 128];   // [h][l=0..128][2n interleaved re/im]
static __device__ __align__(16) float g_CB [H_ * 128];         // [h][2n] CB complex
static __device__ __align__(16) float g_Kk [H_ * CHK];         // conv kernel K[h][l]
static __device__ __align__(16) float g_WAT[H_ * 128 * 128];   // A-matrix for GEMM-A: [h][m][j]
static __device__ __align__(16) float g_QT [H_ * CHK * KC_];   // A-matrix for GEMM-C: [h][t][k]
static __device__ __align__(16) float g_V  [H_ * KC_ * COLS_]; // B-matrix: rows 0..127 = Sin(re,im), 128..255 = u
static __device__ __align__(16) float g_P  [H_ * 128 * COLS_]; // chunk summaries
static __device__ __align__(16) float g_G  [H_ * COLS_ * CHK]; // gelu(y), layout [h][col=(b,c)][t]
static __device__ double g_part[B_ * 64 * 2];
static __device__ float  g_mstd[B_ * 2];

__device__ __forceinline__ float gelu_f(float v) {
    return 0.5f * v * (1.0f + erff(v * 0.70710678118654752f));
}

// ---------------- precompute: powers of w = exp(dt*A), CB = C*B*dt ----------------
__global__ void k_pow(const float* __restrict__ Are, const float* __restrict__ Aim,
                      const float* __restrict__ Bre, const float* __restrict__ Bim,
                      const float* __restrict__ Cre, const float* __restrict__ Cim,
                      const float* __restrict__ logdt) {
    int h = blockIdx.x / 129;
    int l = blockIdx.x % 129;
    int n = threadIdx.x;                 // 0..63
    float dt = expf(logdt[h]);
    int hn = h * SN + n;
    float are = Are[hn] * dt, aim = Aim[hn] * dt;
    float mag = expf(are * (float)l);
    float s, c;
    sincosf(aim * (float)l, &s, &c);
    int base = (h * 129 + l) * 128;
    g_pow[base + 2 * n]     = mag * c;
    g_pow[base + 2 * n + 1] = mag * s;
    if (l == 0) {
        float cbre = (Cre[hn] * Bre[hn] - Cim[hn] * Bim[hn]) * dt;
        float cbim = (Cre[hn] * Bim[hn] + Cim[hn] * Bre[hn]) * dt;
        g_CB[h * 128 + 2 * n]     = cbre;
        g_CB[h * 128 + 2 * n + 1] = cbim;
    }
}

// WAT[h][m][j]: m<64 -> Re(w_m^(127-j)), m>=64 -> Im(w_(m-64)^(127-j))
__global__ void k_WAT() {
    int h = blockIdx.x >> 7;
    int j = blockIdx.x & 127;
    int m = threadIdx.x;                 // 0..127
    int l = 127 - j;
    int pb = (h * 129 + l) * 128;
    float v = (m < 64) ? g_pow[pb + 2 * m] : g_pow[pb + 2 * (m - 64) + 1];
    g_WAT[(h * 128 + m) * 128 + j] = v;
}

// K[h][l] = Re(sum_n CB_n * w_n^l)
__global__ void k_K() {
    int h = blockIdx.x;
    int l = threadIdx.x;                 // 0..127
    const float* pw = &g_pow[(h * 129 + l) * 128];
    const float* cb = &g_CB[h * 128];
    float acc = 0.f;
    #pragma unroll 8
    for (int n = 0; n < SN; n++)
        acc += cb[2 * n] * pw[2 * n] - cb[2 * n + 1] * pw[2 * n + 1];
    g_Kk[h * CHK + l] = acc;
}

// QT[h][t][k]: k<64 -> Re(CB*w^(t+1)); 64..127 -> -Im(CB*w^(t+1));
//              k>=128 (j=k-128): Toeplitz K[t-j] for j<t, K[0]+D for j==t, else 0
__global__ void k_QT(const float* __restrict__ Dv) {
    int h = blockIdx.x >> 7;
    int t = blockIdx.x & 127;
    int k = threadIdx.x;                 // 0..255
    float v;
    if (k < 128) {
        int n = k & 63;
        const float* pw = &g_pow[(h * 129 + t + 1) * 128];
        float cbre = g_CB[h * 128 + 2 * n], cbim = g_CB[h * 128 + 2 * n + 1];
        float pr = pw[2 * n], pi = pw[2 * n + 1];
        v = (k < 64) ? (cbre * pr - cbim * pi) : -(cbre * pi + cbim * pr);
    } else {
        int j = k - 128;
        if (j < t)       v = g_Kk[h * CHK + (t - j)];
        else if (j == t) v = g_Kk[h * CHK] + Dv[h];
        else             v = 0.f;
    }
    g_QT[(h * CHK + t) * KC_ + k] = v;
}

// ---------------- LayerNorm over (L,H) per batch ----------------
__global__ void k_lnpart(const float* __restrict__ x) {
    int b = blockIdx.x, s = blockIdx.y;
    const float* p = x + (size_t)b * (L_ * H_) + (size_t)s * 8192;
    double su = 0.0, sq = 0.0;
    for (int i = threadIdx.x; i < 8192; i += 256) {
        float v = p[i];
        su += (double)v;
        sq += (double)v * (double)v;
    }
    __shared__ double shs[256], shq[256];
    shs[threadIdx.x] = su; shq[threadIdx.x] = sq;
    __syncthreads();
    for (int o = 128; o > 0; o >>= 1) {
        if (threadIdx.x < o) {
            shs[threadIdx.x] += shs[threadIdx.x + o];
            shq[threadIdx.x] += shq[threadIdx.x + o];
        }
        __syncthreads();
    }
    if (threadIdx.x == 0) {
        g_part[(b * 64 + s) * 2]     = shs[0];
        g_part[(b * 64 + s) * 2 + 1] = shq[0];
    }
}

__global__ void k_lnfinal() {
    int b = blockIdx.x, t = threadIdx.x;   // 64 threads
    __shared__ double shs[64], shq[64];
    shs[t] = g_part[(b * 64 + t) * 2];
    shq[t] = g_part[(b * 64 + t) * 2 + 1];
    __syncthreads();
    for (int o = 32; o > 0; o >>= 1) {
        if (t < o) { shs[t] += shs[t + o]; shq[t] += shq[t + o]; }
        __syncthreads();
    }
    if (t == 0) {
        double inv = 1.0 / (double)(L_ * H_);
        double mean = shs[0] * inv;
        double var  = shq[0] * inv - mean * mean;
        g_mstd[2 * b]     = (float)mean;
        g_mstd[2 * b + 1] = (float)(1.0 / sqrt(var + 1e-5));
    }
}

// ---------------- normalize + transpose into V u-rows: V[h][128+j][b*32+c] ----------------
__global__ void k_xpose(const float* __restrict__ x) {
    int b = blockIdx.x, j = blockIdx.y;
    int tid = threadIdx.x;               // 128
    float mean = g_mstd[2 * b], rstd = g_mstd[2 * b + 1];
    __shared__ float sx[32 * 129];
    for (int c = 0; c < 32; c++) {
        float v = x[((size_t)b * L_ + (size_t)c * 128 + j) * H_ + tid];
        sx[c * 129 + tid] = (v - mean) * rstd;
    }
    __syncthreads();
    int w = tid >> 5, lane = tid & 31;
    for (int h0 = w; h0 < 128; h0 += 4)
        g_V[(h0 * KC_ + 128 + j) * COLS_ + b * 32 + lane] = sx[lane * 129 + h0];
}

// ---------------- GEMM-A: P[h][m][col] = sum_j WAT[h][m][j] * u[j][col] ----------------
__global__ __launch_bounds__(256) void k_gemmA() {
    int h = blockIdx.x >> 2, ct = blockIdx.x & 3;
    int col0 = ct * 128;
    __shared__ __align__(16) float As[32 * 133];
    __shared__ __align__(16) float Bs[32 * 132];
    int tid = threadIdx.x, tx = tid & 15, ty = tid >> 4;
    float acc[8][8] = {};
    const float* Asrc = &g_WAT[h * 128 * 128];
    const float* Bsrc = &g_V[(h * KC_ + 128) * COLS_];
    for (int k0 = 0; k0 < 128; k0 += 32) {
        for (int idx = tid; idx < 4096; idx += 256) {
            int r = idx >> 5, kk = idx & 31;
            As[kk * 133 + r] = Asrc[r * 128 + k0 + kk];
        }
        for (int idx = tid; idx < 4096; idx += 256) {
            int kk = idx >> 7, col = idx & 127;
            Bs[kk * 132 + col] = Bsrc[(k0 + kk) * COLS_ + col0 + col];
        }
        __syncthreads();
        #pragma unroll 4
        for (int kk = 0; kk < 32; kk++) {
            float a[8], bb[8];
            #pragma unroll
            for (int i = 0; i < 8; i++) a[i] = As[kk * 133 + ty * 8 + i];
            float4 b0 = *(const float4*)&Bs[kk * 132 + tx * 8];
            float4 b1v = *(const float4*)&Bs[kk * 132 + tx * 8 + 4];
            bb[0]=b0.x; bb[1]=b0.y; bb[2]=b0.z; bb[3]=b0.w;
            bb[4]=b1v.x; bb[5]=b1v.y; bb[6]=b1v.z; bb[7]=b1v.w;
            #pragma unroll
            for (int i = 0; i < 8; i++)
                #pragma unroll
                for (int jj = 0; jj < 8; jj++) acc[i][jj] += a[i] * bb[jj];
        }
        __syncthreads();
    }
    float* Od = &g_P[h * 128 * COLS_];
    #pragma unroll
    for (int i = 0; i < 8; i++) {
        int r = ty * 8 + i;
        float4 v0 = make_float4(acc[i][0], acc[i][1], acc[i][2], acc[i][3]);
        float4 v1 = make_float4(acc[i][4], acc[i][5], acc[i][6], acc[i][7]);
        *(float4*)&Od[r * COLS_ + col0 + tx * 8]     = v0;
        *(float4*)&Od[r * COLS_ + col0 + tx * 8 + 4] = v1;
    }
}

// ---------------- prefix over chunks: Sin(c) = wC*Sin(c-1) + P(c-1), write V rows 0..127 ----------------
__global__ void k_prefix() {
    int h = blockIdx.x & 127, b = blockIdx.x >> 7;
    __shared__ float sP[128 * 33], sS[128 * 33];
    int tid = threadIdx.x;               // 64
    for (int idx = tid; idx < 128 * 32; idx += 64) {
        int k = idx >> 5, c = idx & 31;
        sP[k * 33 + c] = g_P[(h * 128 + k) * COLS_ + b * 32 + c];
    }
    __syncthreads();
    {
        int n = tid;
        float wre = g_pow[(h * 129 + 128) * 128 + 2 * n];
        float wim = g_pow[(h * 129 + 128) * 128 + 2 * n + 1];
        float sre = 0.f, sim = 0.f;
        for (int c = 0; c < 32; c++) {
            sS[n * 33 + c]        = sre;
            sS[(64 + n) * 33 + c] = sim;
            float pre = sP[n * 33 + c], pim = sP[(64 + n) * 33 + c];
            float nr = wre * sre - wim * sim + pre;
            sim = wre * sim + wim * sre + pim;
            sre = nr;
        }
    }
    __syncthreads();
    for (int idx = tid; idx < 128 * 32; idx += 64) {
        int k = idx >> 5, c = idx & 31;
        g_V[(h * KC_ + k) * COLS_ + b * 32 + c] = sS[k * 33 + c];
    }
}

// ---------------- GEMM-C: y = QT * V (carry + local Toeplitz conv + D*u), fused GELU ----------------
__global__ __launch_bounds__(256) void k_gemmC() {
    int h = blockIdx.x >> 2, ct = blockIdx.x & 3;
    int col0 = ct * 128;
    __shared__ __align__(16) float As[32 * 133];
    __shared__ __align__(16) float Bs[32 * 132];
    int tid = threadIdx.x, tx = tid & 15, ty = tid >> 4;
    float acc[8][8] = {};
    const float* Asrc = &g_QT[h * CHK * KC_];
    const float* Bsrc = &g_V[h * KC_ * COLS_];
    for (int k0 = 0; k0 < KC_; k0 += 32) {
        for (int idx = tid; idx < 4096; idx += 256) {
            int r = idx >> 5, kk = idx & 31;
            As[kk * 133 + r] = Asrc[r * KC_ + k0 + kk];
        }
        for (int idx = tid; idx < 4096; idx += 256) {
            int kk = idx >> 7, col = idx & 127;
            Bs[kk * 132 + col] = Bsrc[(k0 + kk) * COLS_ + col0 + col];
        }
        __syncthreads();
        #pragma unroll 4
        for (int kk = 0; kk < 32; kk++) {
            float a[8], bb[8];
            #pragma unroll
            for (int i = 0; i < 8; i++) a[i] = As[kk * 133 + ty * 8 + i];
            float4 b0 = *(const float4*)&Bs[kk * 132 + tx * 8];
            float4 b1v = *(const float4*)&Bs[kk * 132 + tx * 8 + 4];
            bb[0]=b0.x; bb[1]=b0.y; bb[2]=b0.z; bb[3]=b0.w;
            bb[4]=b1v.x; bb[5]=b1v.y; bb[6]=b1v.z; bb[7]=b1v.w;
            #pragma unroll
            for (int i = 0; i < 8; i++)
                #pragma unroll
                for (int jj = 0; jj < 8; jj++) acc[i][jj] += a[i] * bb[jj];
        }
        __syncthreads();
    }
    // epilogue: GELU, store G[h][col][t] (t contiguous)
    float* Gd = &g_G[h * COLS_ * CHK];
    #pragma unroll
    for (int jj = 0; jj < 8; jj++) {
        int col = col0 + tx * 8 + jj;
        float4 v0 = make_float4(gelu_f(acc[0][jj]), gelu_f(acc[1][jj]),
                                gelu_f(acc[2][jj]), gelu_f(acc[3][jj]));
        float4 v1 = make_float4(gelu_f(acc[4][jj]), gelu_f(acc[5][jj]),
                                gelu_f(acc[6][jj]), gelu_f(acc[7][jj]));
        *(float4*)&Gd[col * CHK + ty * 8]     = v0;
        *(float4*)&Gd[col * CHK + ty * 8 + 4] = v1;
    }
}

// ---------------- GEMM-D: out[b][l][o] = sum_h G * W1[o][h] + b1[o] + x ----------------
__global__ __launch_bounds__(256) void k_gemmD(const float* __restrict__ x,
                                               const float* __restrict__ W1,
                                               const float* __restrict__ b1,
                                               float* __restrict__ out) {
    int col = blockIdx.x;                // (b,c)
    int b = col >> 5, c = col & 31;
    __shared__ __align__(16) float As[32 * 132];
    __shared__ __align__(16) float Ws[32 * 132];
    int tid = threadIdx.x, tx = tid & 15, ty = tid >> 4;
    float acc[8][8] = {};
    for (int h0 = 0; h0 < 128; h0 += 32) {
        for (int idx = tid; idx < 4096; idx += 256) {
            int kk = idx >> 7, t = idx & 127;
            As[kk * 132 + t] = g_G[((h0 + kk) * COLS_ + col) * CHK + t];
        }
        for (int idx = tid; idx < 4096; idx += 256) {
            int o = idx >> 5, kk = idx & 31;
            Ws[kk * 132 + o] = W1[o * H_ + h0 + kk];
        }
        __syncthreads();
        #pragma unroll 4
        for (int kk = 0; kk < 32; kk++) {
            float a[8], bb[8];
            #pragma unroll
            for (int i = 0; i < 8; i++) a[i] = As[kk * 132 + ty * 8 + i];
            float4 b0 = *(const float4*)&Ws[kk * 132 + tx * 8];
            float4 b1v = *(const float4*)&Ws[kk * 132 + tx * 8 + 4];
            bb[0]=b0.x; bb[1]=b0.y; bb[2]=b0.z; bb[3]=b0.w;
            bb[4]=b1v.x; bb[5]=b1v.y; bb[6]=b1v.z; bb[7]=b1v.w;
            #pragma unroll
            for (int i = 0; i < 8; i++)
                #pragma unroll
                for (int jj = 0; jj < 8; jj++) acc[i][jj] += a[i] * bb[jj];
        }
        __syncthreads();
    }
    float4 bv0 = *(const float4*)&b1[tx * 8];
    float4 bv1 = *(const float4*)&b1[tx * 8 + 4];
    #pragma unroll
    for (int i = 0; i < 8; i++) {
        int l = c * 128 + ty * 8 + i;
        size_t base = ((size_t)b * L_ + l) * H_ + tx * 8;
        float4 x0 = *(const float4*)&x[base];
        float4 x1 = *(const float4*)&x[base + 4];
        float4 o0 = make_float4(acc[i][0] + bv0.x + x0.x, acc[i][1] + bv0.y + x0.y,
                                acc[i][2] + bv0.z + x0.z, acc[i][3] + bv0.w + x0.w);
        float4 o1 = make_float4(acc[i][4] + bv1.x + x1.x, acc[i][5] + bv1.y + x1.y,
                                acc[i][6] + bv1.z + x1.z, acc[i][7] + bv1.w + x1.w);
        *(float4*)&out[base]     = o0;
        *(float4*)&out[base + 4] = o1;
    }
}

// ---------------- launch ----------------
extern "C" void kernel_launch(void* const* d_in, const int* in_sizes, int n_in,
                              void* d_out, int out_size) {
    const float* x     = (const float*)d_in[0];
    const float* Are   = (const float*)d_in[1];
    const float* Aim   = (const float*)d_in[2];
    const float* Bre   = (const float*)d_in[3];
    const float* Bim   = (const float*)d_in[4];
    const float* Cre   = (const float*)d_in[5];
    const float* Cim   = (const float*)d_in[6];
    const float* Dv    = (const float*)d_in[7];
    const float* logdt = (const float*)d_in[8];
    const float* W1    = (const float*)d_in[9];
    const float* b1    = (const float*)d_in[10];
    float* out = (float*)d_out;

    k_pow<<<H_ * 129, 64>>>(Are, Aim, Bre, Bim, Cre, Cim, logdt);
    k_WAT<<<H_ * 128, 128>>>();
    k_K<<<H_, 128>>>();
    k_QT<<<H_ * 128, 256>>>(Dv);
    k_lnpart<<<dim3(B_, 64), 256>>>(x);
    k_lnfinal<<<B_, 64>>>();
    k_xpose<<<dim3(B_, CHK), 128>>>(x);
    k_gemmA<<<H_ * 4, 256>>>();
    k_prefix<<<B_ * H_, 64>>>();
    k_gemmC<<<H_ * 4, 256>>>();
    k_gemmD<<<COLS_, 256>>>(x, W1, b1, out);
}

// round 2
// speedup vs baseline: 1.4698x; 1.4698x over previous
#include <cuda_runtime.h>
#include <math.h>

// Problem dims
#define H_    128
#define B_    16
#define L_    4096
#define SN    64      // SSM state size N
#define CHK   128     // chunk length
#define NCH   32      // chunks (L/CHK)
#define COLS_ 512     // B_*NCH
#define KC_   256     // GEMM-C K dim (2*SN + CHK)
#define PLD   132     // padded stride for power rows (l = 0..128)

// ---------------- device scratch ----------------
static __device__ __align__(16) float g_pow2[H_ * 128 * PLD];  // [h][chan(2n=re,2n+1=im)][l]
static __device__ __align__(16) float g_CB [H_ * 128];         // [h][2n]
static __device__ __align__(16) float g_Kk [H_ * CHK];         // K[h][l]
static __device__ __align__(16) float g_QT [H_ * CHK * KC_];   // [h][t][k]
static __device__ __align__(16) float g_V  [H_ * KC_ * COLS_]; // rows 0..127 Sin(re,im), 128..255 u
static __device__ __align__(16) float g_P  [H_ * 128 * COLS_];
static __device__ __align__(16) float g_G  [H_ * COLS_ * CHK]; // [h][col][t]
static __device__ double g_part[B_ * 64 * 2];
static __device__ float  g_mstd[B_ * 2];

__device__ __forceinline__ float gelu_f(float v) {
    return 0.5f * v * (1.0f + erff(v * 0.70710678118654752f));
}
__device__ __forceinline__ unsigned f2tf(float f) {
    unsigned u; asm("cvt.rna.tf32.f32 %0, %1;" : "=r"(u) : "f"(f)); return u;
}
__device__ __forceinline__ void mma8(float* d, const unsigned* a, const unsigned* b) {
    asm volatile("mma.sync.aligned.m16n8k8.row.col.f32.tf32.tf32.f32 "
        "{%0,%1,%2,%3}, {%4,%5,%6,%7}, {%8,%9}, {%0,%1,%2,%3};"
        : "+f"(d[0]), "+f"(d[1]), "+f"(d[2]), "+f"(d[3])
        : "r"(a[0]), "r"(a[1]), "r"(a[2]), "r"(a[3]), "r"(b[0]), "r"(b[1]));
}

// ---------------- precompute: powers via complex recurrence ----------------
__global__ void k_pow(const float* __restrict__ Are, const float* __restrict__ Aim,
                      const float* __restrict__ Bre, const float* __restrict__ Bim,
                      const float* __restrict__ Cre, const float* __restrict__ Cim,
                      const float* __restrict__ logdt) {
    int h = blockIdx.x;
    int n = threadIdx.x;                 // 0..63
    float dt = expf(logdt[h]);
    int hn = h * SN + n;
    float are = Are[hn] * dt, aim = Aim[hn] * dt;
    float mag = expf(are);
    float s, c; sincosf(aim, &s, &c);
    float wre = mag * c, wim = mag * s;          // w = exp(dt*A)
    float pre = 1.f, pim = 0.f;
    float* rowr = &g_pow2[(h * 128 + 2 * n) * PLD];
    float* rowi = &g_pow2[(h * 128 + 2 * n + 1) * PLD];
    #pragma unroll 4
    for (int l = 0; l <= 128; l++) {
        rowr[l] = pre; rowi[l] = pim;
        float nr = wre * pre - wim * pim;
        pim = wre * pim + wim * pre;
        pre = nr;
    }
    float cbre = (Cre[hn] * Bre[hn] - Cim[hn] * Bim[hn]) * dt;
    float cbim = (Cre[hn] * Bim[hn] + Cim[hn] * Bre[hn]) * dt;
    g_CB[h * 128 + 2 * n]     = cbre;
    g_CB[h * 128 + 2 * n + 1] = cbim;
}

// K[h][l] = Re(sum_n CB_n * w_n^l)
__global__ void k_K() {
    int h = blockIdx.x;
    int l = threadIdx.x;                 // 0..127
    const float* cb = &g_CB[h * 128];
    float acc = 0.f;
    #pragma unroll 8
    for (int n = 0; n < SN; n++)
        acc += cb[2 * n]     * g_pow2[(h * 128 + 2 * n) * PLD + l]
             - cb[2 * n + 1] * g_pow2[(h * 128 + 2 * n + 1) * PLD + l];
    g_Kk[h * CHK + l] = acc;
}

// QT[h][t][k]: k<64 Re(CB*w^(t+1)); 64..127 -Im(CB*w^(t+1)); k>=128 Toeplitz K
__global__ void k_QT(const float* __restrict__ Dv) {
    int h = blockIdx.x;
    int k = threadIdx.x;                 // 0..255
    float cr = 0.f, ci = 0.f;
    const float* pr = 0; const float* pi = 0;
    if (k < 128) {
        int n = k & 63;
        cr = g_CB[h * 128 + 2 * n]; ci = g_CB[h * 128 + 2 * n + 1];
        pr = &g_pow2[(h * 128 + 2 * n) * PLD];
        pi = &g_pow2[(h * 128 + 2 * n + 1) * PLD];
    }
    float K0D = g_Kk[h * CHK] + Dv[h];
    for (int t = 0; t < CHK; t++) {
        float v;
        if (k < 64)       v =  cr * pr[t + 1] - ci * pi[t + 1];
        else if (k < 128) v = -(cr * pi[t + 1] + ci * pr[t + 1]);
        else {
            int j = k - 128;
            v = (j < t) ? g_Kk[h * CHK + (t - j)] : (j == t ? K0D : 0.f);
        }
        g_QT[(h * CHK + t) * KC_ + k] = v;
    }
}

// ---------------- LayerNorm over (L,H) per batch ----------------
__global__ void k_lnpart(const float* __restrict__ x) {
    int b = blockIdx.x, s = blockIdx.y;
    const float* p = x + (size_t)b * (L_ * H_) + (size_t)s * 8192;
    double su = 0.0, sq = 0.0;
    for (int i = threadIdx.x; i < 8192; i += 256) {
        float v = p[i];
        su += (double)v; sq += (double)v * (double)v;
    }
    __shared__ double shs[256], shq[256];
    shs[threadIdx.x] = su; shq[threadIdx.x] = sq;
    __syncthreads();
    for (int o = 128; o > 0; o >>= 1) {
        if (threadIdx.x < o) {
            shs[threadIdx.x] += shs[threadIdx.x + o];
            shq[threadIdx.x] += shq[threadIdx.x + o];
        }
        __syncthreads();
    }
    if (threadIdx.x == 0) {
        g_part[(b * 64 + s) * 2]     = shs[0];
        g_part[(b * 64 + s) * 2 + 1] = shq[0];
    }
}

__global__ void k_lnfinal() {
    int b = blockIdx.x, t = threadIdx.x;   // 64 threads
    __shared__ double shs[64], shq[64];
    shs[t] = g_part[(b * 64 + t) * 2];
    shq[t] = g_part[(b * 64 + t) * 2 + 1];
    __syncthreads();
    for (int o = 32; o > 0; o >>= 1) {
        if (t < o) { shs[t] += shs[t + o]; shq[t] += shq[t + o]; }
        __syncthreads();
    }
    if (t == 0) {
        double inv = 1.0 / (double)(L_ * H_);
        double mean = shs[0] * inv;
        double var  = shq[0] * inv - mean * mean;
        g_mstd[2 * b]     = (float)mean;
        g_mstd[2 * b + 1] = (float)(1.0 / sqrt(var + 1e-5));
    }
}

// ---------------- normalize + transpose into V u-rows ----------------
__global__ void k_xpose(const float* __restrict__ x) {
    int b = blockIdx.x, j = blockIdx.y;
    int tid = threadIdx.x;               // 128
    float mean = g_mstd[2 * b], rstd = g_mstd[2 * b + 1];
    __shared__ float sx[32 * 129];
    for (int c = 0; c < 32; c++) {
        float v = x[((size_t)b * L_ + (size_t)c * 128 + j) * H_ + tid];
        sx[c * 129 + tid] = (v - mean) * rstd;
    }
    __syncthreads();
    int w = tid >> 5, lane = tid & 31;
    for (int h0 = w; h0 < 128; h0 += 4)
        g_V[(h0 * KC_ + 128 + j) * COLS_ + b * 32 + lane] = sx[lane * 129 + h0];
}

// ---------------- tf32 GEMM core helpers ----------------
// 8 warps: wm = warp&1 (2 x 64 rows), wn = warp>>1 (4 x 32 cols). Warp tile 64x32.
// As[m][k] stride 36, Bs[n][k] stride 36, tf32 bits.

#define GEMM_COMPUTE_PANEL(As, Bs, acc, wm, wn, g, tg)                         \
    _Pragma("unroll")                                                          \
    for (int ks = 0; ks < 32; ks += 8) {                                       \
        unsigned a[4][4], bf[4][2];                                            \
        _Pragma("unroll")                                                      \
        for (int mt = 0; mt < 4; mt++) {                                       \
            int r = (wm) * 64 + mt * 16 + (g);                                 \
            a[mt][0] = As[r * 36 + ks + (tg)];                                 \
            a[mt][1] = As[(r + 8) * 36 + ks + (tg)];                           \
            a[mt][2] = As[r * 36 + ks + (tg) + 4];                             \
            a[mt][3] = As[(r + 8) * 36 + ks + (tg) + 4];                       \
        }                                                                      \
        _Pragma("unroll")                                                      \
        for (int nt = 0; nt < 4; nt++) {                                       \
            int nn = (wn) * 32 + nt * 8 + (g);                                 \
            bf[nt][0] = Bs[nn * 36 + ks + (tg)];                               \
            bf[nt][1] = Bs[nn * 36 + ks + (tg) + 4];                           \
        }                                                                      \
        _Pragma("unroll")                                                      \
        for (int mt = 0; mt < 4; mt++)                                         \
            _Pragma("unroll")                                                  \
            for (int nt = 0; nt < 4; nt++)                                     \
                mma8(acc[mt][nt], a[mt], bf[nt]);                              \
    }

// ---------------- GEMM-A: P[m][col] = sum_j WAT[m][j] * u[j][col] ----------------
__global__ __launch_bounds__(256) void k_gemmA() {
    int h = blockIdx.x >> 2, col0 = (blockIdx.x & 3) * 128;
    __shared__ unsigned As[128 * 36], Bs[128 * 36];
    int tid = threadIdx.x, lane = tid & 31, warp = tid >> 5;
    int wm = warp & 1, wn = warp >> 1, g = lane >> 2, tg = lane & 3;
    float acc[4][4][4] = {};
    for (int k0 = 0; k0 < 128; k0 += 32) {
        for (int idx = tid; idx < 4096; idx += 256) {
            int m = idx >> 5, kk = idx & 31;
            int chan = (m < 64) ? 2 * m : 2 * (m - 64) + 1;
            As[m * 36 + kk] = f2tf(g_pow2[(h * 128 + chan) * PLD + 127 - (k0 + kk)]);
        }
        for (int idx = tid; idx < 4096; idx += 256) {
            int kk = idx >> 7, col = idx & 127;
            Bs[col * 36 + kk] = f2tf(g_V[(h * KC_ + 128 + k0 + kk) * COLS_ + col0 + col]);
        }
        __syncthreads();
        GEMM_COMPUTE_PANEL(As, Bs, acc, wm, wn, g, tg);
        __syncthreads();
    }
    float* Od = &g_P[h * 128 * COLS_];
    #pragma unroll
    for (int mt = 0; mt < 4; mt++)
        #pragma unroll
        for (int nt = 0; nt < 4; nt++) {
            int r0 = wm * 64 + mt * 16 + g;
            int c = col0 + wn * 32 + nt * 8 + 2 * tg;
            *(float2*)&Od[r0 * COLS_ + c]       = make_float2(acc[mt][nt][0], acc[mt][nt][1]);
            *(float2*)&Od[(r0 + 8) * COLS_ + c] = make_float2(acc[mt][nt][2], acc[mt][nt][3]);
        }
}

// ---------------- prefix over chunks ----------------
__global__ void k_prefix() {
    int h = blockIdx.x & 127, b = blockIdx.x >> 7;
    __shared__ float sP[128 * 33], sS[128 * 33];
    int tid = threadIdx.x;               // 64
    for (int idx = tid; idx < 128 * 32; idx += 64) {
        int k = idx >> 5, c = idx & 31;
        sP[k * 33 + c] = g_P[(h * 128 + k) * COLS_ + b * 32 + c];
    }
    __syncthreads();
    {
        int n = tid;
        float wre = g_pow2[(h * 128 + 2 * n) * PLD + 128];
        float wim = g_pow2[(h * 128 + 2 * n + 1) * PLD + 128];
        float sre = 0.f, sim = 0.f;
        for (int c = 0; c < 32; c++) {
            sS[n * 33 + c]        = sre;
            sS[(64 + n) * 33 + c] = sim;
            float pre = sP[n * 33 + c], pim = sP[(64 + n) * 33 + c];
            float nr = wre * sre - wim * sim + pre;
            sim = wre * sim + wim * sre + pim;
            sre = nr;
        }
    }
    __syncthreads();
    for (int idx = tid; idx < 128 * 32; idx += 64) {
        int k = idx >> 5, c = idx & 31;
        g_V[(h * KC_ + k) * COLS_ + b * 32 + c] = sS[k * 33 + c];
    }
}

// ---------------- GEMM-C: G[col][t] = gelu( sum_k V[k][col] * QT[t][k] ) ----------------
// M = col (128 of 512), N = t (128), K = 256.
__global__ __launch_bounds__(256) void k_gemmC() {
    int h = blockIdx.x >> 2, col0 = (blockIdx.x & 3) * 128;
    __shared__ unsigned As[128 * 36], Bs[128 * 36];
    int tid = threadIdx.x, lane = tid & 31, warp = tid >> 5;
    int wm = warp & 1, wn = warp >> 1, g = lane >> 2, tg = lane & 3;
    float acc[4][4][4] = {};
    for (int k0 = 0; k0 < KC_; k0 += 32) {
        for (int idx = tid; idx < 4096; idx += 256) {
            int kk = idx >> 7, col = idx & 127;
            As[col * 36 + kk] = f2tf(g_V[(h * KC_ + k0 + kk) * COLS_ + col0 + col]);
        }
        for (int idx = tid; idx < 1024; idx += 256) {
            int t = idx >> 3, k4 = (idx & 7) * 4;
            float4 v = *(const float4*)&g_QT[(h * CHK + t) * KC_ + k0 + k4];
            Bs[t * 36 + k4]     = f2tf(v.x);
            Bs[t * 36 + k4 + 1] = f2tf(v.y);
            Bs[t * 36 + k4 + 2] = f2tf(v.z);
            Bs[t * 36 + k4 + 3] = f2tf(v.w);
        }
        __syncthreads();
        GEMM_COMPUTE_PANEL(As, Bs, acc, wm, wn, g, tg);
        __syncthreads();
    }
    float* Gd = &g_G[h * COLS_ * CHK];
    #pragma unroll
    for (int mt = 0; mt < 4; mt++)
        #pragma unroll
        for (int nt = 0; nt < 4; nt++) {
            int r0 = col0 + wm * 64 + mt * 16 + g;       // col
            int c = wn * 32 + nt * 8 + 2 * tg;           // t
            *(float2*)&Gd[r0 * CHK + c] =
                make_float2(gelu_f(acc[mt][nt][0]), gelu_f(acc[mt][nt][1]));
            *(float2*)&Gd[(r0 + 8) * CHK + c] =
                make_float2(gelu_f(acc[mt][nt][2]), gelu_f(acc[mt][nt][3]));
        }
}

// ---------------- GEMM-D: out[t][o] = sum_h G[h][col][t] * W1[o][h] + b1 + x ----------------
__global__ __launch_bounds__(256) void k_gemmD(const float* __restrict__ x,
                                               const float* __restrict__ W1,
                                               const float* __restrict__ b1,
                                               float* __restrict__ out) {
    int col = blockIdx.x;                // (b,c)
    int b = col >> 5, c = col & 31;
    __shared__ unsigned As[128 * 36], Bs[128 * 36];
    int tid = threadIdx.x, lane = tid & 31, warp = tid >> 5;
    int wm = warp & 1, wn = warp >> 1, g = lane >> 2, tg = lane & 3;
    float acc[4][4][4] = {};
    for (int h0 = 0; h0 < 128; h0 += 32) {
        for (int idx = tid; idx < 4096; idx += 256) {
            int kk = idx >> 7, t = idx & 127;
            As[t * 36 + kk] = f2tf(g_G[((h0 + kk) * COLS_ + col) * CHK + t]);
        }
        for (int idx = tid; idx < 1024; idx += 256) {
            int o = idx >> 3, k4 = (idx & 7) * 4;
            float4 v = *(const float4*)&W1[o * H_ + h0 + k4];
            Bs[o * 36 + k4]     = f2tf(v.x);
            Bs[o * 36 + k4 + 1] = f2tf(v.y);
            Bs[o * 36 + k4 + 2] = f2tf(v.z);
            Bs[o * 36 + k4 + 3] = f2tf(v.w);
        }
        __syncthreads();
        GEMM_COMPUTE_PANEL(As, Bs, acc, wm, wn, g, tg);
        __syncthreads();
    }
    #pragma unroll
    for (int mt = 0; mt < 4; mt++)
        #pragma unroll
        for (int nt = 0; nt < 4; nt++) {
            int t0 = wm * 64 + mt * 16 + g;
            int o  = wn * 32 + nt * 8 + 2 * tg;
            float2 bias = *(const float2*)&b1[o];
            size_t base0 = ((size_t)b * L_ + c * 128 + t0) * H_ + o;
            size_t base1 = ((size_t)b * L_ + c * 128 + t0 + 8) * H_ + o;
            float2 x0 = *(const float2*)&x[base0];
            float2 x1 = *(const float2*)&x[base1];
            *(float2*)&out[base0] = make_float2(acc[mt][nt][0] + bias.x + x0.x,
                                                acc[mt][nt][1] + bias.y + x0.y);
            *(float2*)&out[base1] = make_float2(acc[mt][nt][2] + bias.x + x1.x,
                                                acc[mt][nt][3] + bias.y + x1.y);
        }
}

// ---------------- launch ----------------
extern "C" void kernel_launch(void* const* d_in, const int* in_sizes, int n_in,
                              void* d_out, int out_size) {
    const float* x     = (const float*)d_in[0];
    const float* Are   = (const float*)d_in[1];
    const float* Aim   = (const float*)d_in[2];
    const float* Bre   = (const float*)d_in[3];
    const float* Bim   = (const float*)d_in[4];
    const float* Cre   = (const float*)d_in[5];
    const float* Cim   = (const float*)d_in[6];
    const float* Dv    = (const float*)d_in[7];
    const float* logdt = (const float*)d_in[8];
    const float* W1    = (const float*)d_in[9];
    const float* b1    = (const float*)d_in[10];
    float* out = (float*)d_out;

    k_pow<<<H_, 64>>>(Are, Aim, Bre, Bim, Cre, Cim, logdt);
    k_K<<<H_, 128>>>();
    k_QT<<<H_, 256>>>(Dv);
    k_lnpart<<<dim3(B_, 64), 256>>>(x);
    k_lnfinal<<<B_, 64>>>();
    k_xpose<<<dim3(B_, CHK), 128>>>(x);
    k_gemmA<<<H_ * 4, 256>>>();
    k_prefix<<<B_ * H_, 64>>>();
    k_gemmC<<<H_ * 4, 256>>>();
    k_gemmD<<<COLS_, 256>>>(x, W1, b1, out);
}

// round 5
// speedup vs baseline: 1.9291x; 1.3125x over previous
#include <cuda_runtime.h>
#include <math.h>

// Problem dims
#define H_    128
#define B_    16
#define L_    4096
#define SN    64      // SSM state size N
#define CHK   128     // chunk length
#define NCH   32      // chunks (L/CHK)
#define COLS_ 512     // B_*NCH
#define KC_   256     // GEMM-C K dim (2*SN + CHK)

// ---------------- device scratch ----------------
static __device__ __align__(16) float g_w  [H_ * 128];         // [h][2n] w = exp(dt*A)
static __device__ __align__(16) float g_wC [H_ * 128];         // [h][2n] w^128
static __device__ __align__(16) float g_CB [H_ * 128];         // [h][2n]
static __device__ __align__(16) float g_Kk [H_ * CHK];         // K[h][l]
static __device__ __align__(16) float g_WAT[H_ * 128 * 128];   // [h][m][j] tf32-rounded
static __device__ __align__(16) float g_QT [H_ * CHK * KC_];   // [h][t][k] tf32-rounded
static __device__ __align__(16) float g_V  [H_ * KC_ * COLS_]; // rows 0..127 Sin, 128..255 u ; tf32
static __device__ __align__(16) float g_G  [H_ * COLS_ * CHK]; // [h][col][t] tf32
static __device__ double g_part[B_ * 32 * 2];
static __device__ float  g_mstd[B_ * 2];

__device__ __forceinline__ float gelu_f(float v) {
    return 0.5f * v * (1.0f + erff(v * 0.70710678118654752f));
}
__device__ __forceinline__ unsigned f2tf(float f) {
    unsigned u; asm("cvt.rna.tf32.f32 %0, %1;" : "=r"(u) : "f"(f)); return u;
}
__device__ __forceinline__ float tf32f(float f) { return __uint_as_float(f2tf(f)); }

__device__ __forceinline__ void mma8(float* d, const unsigned* a, const unsigned* b) {
    asm volatile("mma.sync.aligned.m16n8k8.row.col.f32.tf32.tf32.f32 "
        "{%0,%1,%2,%3}, {%4,%5,%6,%7}, {%8,%9}, {%0,%1,%2,%3};"
        : "+f"(d[0]), "+f"(d[1]), "+f"(d[2]), "+f"(d[3])
        : "r"(a[0]), "r"(a[1]), "r"(a[2]), "r"(a[3]), "r"(b[0]), "r"(b[1]));
}

// ---------------- precompute: powers via tiled recurrence, WAT (coalesced), K ----------------
__global__ __launch_bounds__(256) void k_pow(
                      const float* __restrict__ Are, const float* __restrict__ Aim,
                      const float* __restrict__ Bre, const float* __restrict__ Bim,
                      const float* __restrict__ Cre, const float* __restrict__ Cim,
                      const float* __restrict__ logdt) {
    int h = blockIdx.x, tid = threadIdx.x;   // 256 threads
    __shared__ float st[128 * 33];           // power tile [chan][i]
    __shared__ float scb[128];
    float pre = 0.f, pim = 0.f, wre = 0.f, wim = 0.f;
    if (tid < 64) {
        int n = tid, hn = h * SN + n;
        float dt = expf(logdt[h]);
        float are = Are[hn] * dt, aim = Aim[hn] * dt;
        float mag = expf(are);
        float s, c; sincosf(aim, &s, &c);
        wre = mag * c; wim = mag * s;
        g_w[h * 128 + 2 * n]     = wre;
        g_w[h * 128 + 2 * n + 1] = wim;
        float cbre = (Cre[hn] * Bre[hn] - Cim[hn] * Bim[hn]) * dt;
        float cbim = (Cre[hn] * Bim[hn] + Cim[hn] * Bre[hn]) * dt;
        scb[2 * n] = cbre; scb[2 * n + 1] = cbim;
        g_CB[h * 128 + 2 * n]     = cbre;
        g_CB[h * 128 + 2 * n + 1] = cbim;
        pre = 1.f; pim = 0.f;
    }
    __syncthreads();
    for (int l0 = 0; l0 < 128; l0 += 32) {
        if (tid < 64) {
            int n = tid;
            #pragma unroll 8
            for (int i = 0; i < 32; i++) {
                st[(2 * n) * 33 + i]     = pre;
                st[(2 * n + 1) * 33 + i] = pim;
                float nr = wre * pre - wim * pim;
                pim = wre * pim + wim * pre;
                pre = nr;
            }
        }
        __syncthreads();
        for (int idx = tid; idx < 4096; idx += 256) {
            int chan = idx >> 5, i = idx & 31;
            int m = (chan & 1) ? 64 + (chan >> 1) : (chan >> 1);
            g_WAT[(h * 128 + m) * 128 + 127 - (l0 + i)] = tf32f(st[chan * 33 + i]);
        }
        if (tid >= 64 && tid < 96) {
            int i = tid - 64;
            float a = 0.f;
            #pragma unroll 8
            for (int n = 0; n < 64; n++)
                a += scb[2 * n] * st[(2 * n) * 33 + i]
                   - scb[2 * n + 1] * st[(2 * n + 1) * 33 + i];
            g_Kk[h * CHK + l0 + i] = a;
        }
        __syncthreads();
    }
    if (tid < 64) {                          // state now = w^128
        g_wC[h * 128 + 2 * tid]     = pre;
        g_wC[h * 128 + 2 * tid + 1] = pim;
    }
}

// QT[h][t][k]: k<64 Re(CB*w^(t+1)); 64..127 -Im; k>=128 Toeplitz K. 192 threads.
__global__ __launch_bounds__(192) void k_QT(const float* __restrict__ Dv) {
    int h = blockIdx.x, tid = threadIdx.x;   // 192
    __shared__ float sK[128];
    if (tid < 128) sK[tid] = g_Kk[h * CHK + tid];
    __syncthreads();
    if (tid < 64) {
        int n = tid;
        float wre = g_w[h * 128 + 2 * n], wim = g_w[h * 128 + 2 * n + 1];
        float cr = g_CB[h * 128 + 2 * n], ci = g_CB[h * 128 + 2 * n + 1];
        float qre = cr * wre - ci * wim;     // CB * w^1
        float qim = cr * wim + ci * wre;
        for (int t = 0; t < CHK; t++) {
            g_QT[(h * CHK + t) * KC_ + n]      = tf32f(qre);
            g_QT[(h * CHK + t) * KC_ + 64 + n] = tf32f(-qim);
            float nr = qre * wre - qim * wim;
            qim = qre * wim + qim * wre;
            qre = nr;
        }
    } else {
        int j = tid - 64;                    // 0..127
        float K0D = sK[0] + Dv[h];
        for (int t = 0; t < CHK; t++) {
            float v = (j < t) ? sK[t - j] : (j == t ? K0D : 0.f);
            g_QT[(h * CHK + t) * KC_ + 128 + j] = tf32f(v);
        }
    }
}

// ---------------- LayerNorm over (L,H) per batch ----------------
__global__ __launch_bounds__(256) void k_lnpart(const float* __restrict__ x) {
    int b = blockIdx.x, s = blockIdx.y;      // 16 x 32
    const float4* p = (const float4*)(x + (size_t)b * (L_ * H_)) + (size_t)s * 4096;
    float su = 0.f, sq = 0.f;
    for (int i = threadIdx.x; i < 4096; i += 256) {
        float4 v = p[i];
        su += v.x + v.y + v.z + v.w;
        sq += v.x * v.x + v.y * v.y + v.z * v.z + v.w * v.w;
    }
    double ds = (double)su, dq = (double)sq;
    #pragma unroll
    for (int o = 16; o > 0; o >>= 1) {
        ds += __shfl_down_sync(0xffffffffu, ds, o);
        dq += __shfl_down_sync(0xffffffffu, dq, o);
    }
    __shared__ double ws[8], wq[8];
    int lane = threadIdx.x & 31, warp = threadIdx.x >> 5;
    if (lane == 0) { ws[warp] = ds; wq[warp] = dq; }
    __syncthreads();
    if (threadIdx.x == 0) {
        double S = 0, Q = 0;
        for (int i = 0; i < 8; i++) { S += ws[i]; Q += wq[i]; }
        g_part[(b * 32 + s) * 2]     = S;
        g_part[(b * 32 + s) * 2 + 1] = Q;
    }
}

__global__ void k_lnfinal() {
    int b = blockIdx.x, t = threadIdx.x;     // 32 threads
    double s = g_part[(b * 32 + t) * 2];
    double q = g_part[(b * 32 + t) * 2 + 1];
    #pragma unroll
    for (int o = 16; o > 0; o >>= 1) {
        s += __shfl_down_sync(0xffffffffu, s, o);
        q += __shfl_down_sync(0xffffffffu, q, o);
    }
    if (t == 0) {
        double inv = 1.0 / (double)(L_ * H_);
        double mean = s * inv;
        double var  = q * inv - mean * mean;
        g_mstd[2 * b]     = (float)mean;
        g_mstd[2 * b + 1] = (float)(1.0 / sqrt(var + 1e-5));
    }
}

// ---------------- normalize + transpose into V u-rows (tf32-rounded) ----------------
__global__ __launch_bounds__(128) void k_xpose(const float* __restrict__ x) {
    int b = blockIdx.x, j = blockIdx.y;
    int tid = threadIdx.x;                   // 128
    float mean = g_mstd[2 * b], rstd = g_mstd[2 * b + 1];
    __shared__ float sx[32 * 129];
    #pragma unroll 4
    for (int c = 0; c < 32; c++) {
        float v = x[((size_t)b * L_ + (size_t)c * 128 + j) * H_ + tid];
        sx[c * 129 + tid] = (v - mean) * rstd;
    }
    __syncthreads();
    int w = tid >> 5, lane = tid & 31;
    for (int h0 = w; h0 < 128; h0 += 4)
        g_V[(h0 * KC_ + 128 + j) * COLS_ + b * 32 + lane] = tf32f(sx[lane * 129 + h0]);
}

// ---------------- tf32 GEMM compute panel ----------------
// 8 warps: wm = warp&1 (2 x 64 rows), wn = warp>>1 (4 x 32 cols). Warp tile 64x32.
#define GEMM_COMPUTE_PANEL(As, Bs, acc, wm, wn, g, tg)                         \
    _Pragma("unroll")                                                          \
    for (int ks = 0; ks < 32; ks += 8) {                                       \
        unsigned a[4][4], bf[4][2];                                            \
        _Pragma("unroll")                                                      \
        for (int mt = 0; mt < 4; mt++) {                                       \
            int r = (wm) * 64 + mt * 16 + (g);                                 \
            a[mt][0] = As[r * 36 + ks + (tg)];                                 \
            a[mt][1] = As[(r + 8) * 36 + ks + (tg)];                           \
            a[mt][2] = As[r * 36 + ks + (tg) + 4];                             \
            a[mt][3] = As[(r + 8) * 36 + ks + (tg) + 4];                       \
        }                                                                      \
        _Pragma("unroll")                                                      \
        for (int nt = 0; nt < 4; nt++) {                                       \
            int nn = (wn) * 32 + nt * 8 + (g);                                 \
            bf[nt][0] = Bs[nn * 36 + ks + (tg)];                               \
            bf[nt][1] = Bs[nn * 36 + ks + (tg) + 4];                           \
        }                                                                      \
        _Pragma("unroll")                                                      \
        for (int mt = 0; mt < 4; mt++)                                         \
            _Pragma("unroll")                                                  \
            for (int nt = 0; nt < 4; nt++)                                     \
                mma8(acc[mt][nt], a[mt], bf[nt]);                              \
    }

// ---------------- GEMM-A + fused chunk prefix ----------------
__global__ __launch_bounds__(256) void k_gemmA() {
    extern __shared__ float dyn[];           // 128*133 floats
    unsigned* As = (unsigned*)dyn;
    unsigned* Bs = As + 4608;
    float* sP = dyn;
    int h = blockIdx.x >> 2, col0 = (blockIdx.x & 3) * 128;
    int tid = threadIdx.x, lane = tid & 31, warp = tid >> 5;
    int wm = warp & 1, wn = warp >> 1, g = lane >> 2, tg = lane & 3;
    float acc[4][4][4] = {};
    uint4 ra[4], rb[4];
    const float* srcA = &g_WAT[h * 128 * 128];
    const float* srcB = &g_V[(h * KC_ + 128) * COLS_];

    #define GA_LOADA(k0) { _Pragma("unroll") for (int i = 0; i < 4; i++) {     \
        int idx = tid + i * 256; int m = idx >> 3, kk = (idx & 7) * 4;         \
        ra[i] = *(const uint4*)&srcA[m * 128 + (k0) + kk]; } }
    #define GA_LOADB(k0) { _Pragma("unroll") for (int i = 0; i < 4; i++) {     \
        int idx = tid + i * 256; int kk = idx >> 5, c = (idx & 31) * 4;        \
        rb[i] = *(const uint4*)&srcB[((k0) + kk) * COLS_ + col0 + c]; } }
    #define GA_STORE() { _Pragma("unroll") for (int i = 0; i < 4; i++) {       \
        int idx = tid + i * 256; int m = idx >> 3, kk = (idx & 7) * 4;         \
        *(uint4*)&As[m * 36 + kk] = ra[i]; }                                   \
        _Pragma("unroll") for (int i = 0; i < 4; i++) {                        \
        int idx = tid + i * 256; int kk = idx >> 5, c = (idx & 31) * 4;        \
        Bs[c * 36 + kk] = rb[i].x; Bs[(c + 1) * 36 + kk] = rb[i].y;            \
        Bs[(c + 2) * 36 + kk] = rb[i].z; Bs[(c + 3) * 36 + kk] = rb[i].w; } }

    GA_LOADA(0); GA_LOADB(0); GA_STORE(); __syncthreads();
    for (int k0 = 0; k0 < 128; k0 += 32) {
        bool more = (k0 + 32) < 128;
        if (more) { GA_LOADA(k0 + 32); GA_LOADB(k0 + 32); }
        GEMM_COMPUTE_PANEL(As, Bs, acc, wm, wn, g, tg);
        __syncthreads();
        if (more) { GA_STORE(); __syncthreads(); }
    }
    // stage P into shared [m][col_local], stride 133
    #pragma unroll
    for (int mt = 0; mt < 4; mt++)
        #pragma unroll
        for (int nt = 0; nt < 4; nt++) {
            int r0 = wm * 64 + mt * 16 + g;
            int cl = wn * 32 + nt * 8 + 2 * tg;
            sP[r0 * 133 + cl]           = acc[mt][nt][0];
            sP[r0 * 133 + cl + 1]       = acc[mt][nt][1];
            sP[(r0 + 8) * 133 + cl]     = acc[mt][nt][2];
            sP[(r0 + 8) * 133 + cl + 1] = acc[mt][nt][3];
        }
    __syncthreads();
    // in-place prefix scan over 32 chunks: thread = (b_local, n)
    {
        int n = tid & 63, bl = tid >> 6;
        float wre = g_wC[h * 128 + 2 * n], wim = g_wC[h * 128 + 2 * n + 1];
        float sre = 0.f, sim = 0.f;
        #pragma unroll 4
        for (int c = 0; c < 32; c++) {
            int colI = bl * 32 + c;
            float pr = sP[n * 133 + colI];
            float pi = sP[(64 + n) * 133 + colI];
            sP[n * 133 + colI]        = sre;
            sP[(64 + n) * 133 + colI] = sim;
            float nr = wre * sre - wim * sim + pr;
            sim = wre * sim + wim * sre + pi;
            sre = nr;
        }
    }
    __syncthreads();
    // write Sin rows (tf32-rounded) to g_V rows 0..127
    for (int idx = tid; idx < 16384; idx += 256) {
        int k = idx >> 7, col = idx & 127;
        g_V[(h * KC_ + k) * COLS_ + col0 + col] = tf32f(sP[k * 133 + col]);
    }
    #undef GA_LOADA
    #undef GA_LOADB
    #undef GA_STORE
}

// ---------------- GEMM-C: G[col][t] = gelu( sum_k V[k][col] * QT[t][k] ) ----------------
__global__ __launch_bounds__(256) void k_gemmC() {
    __shared__ unsigned As[128 * 36], Bs[128 * 36];
    int h = blockIdx.x >> 2, col0 = (blockIdx.x & 3) * 128;
    int tid = threadIdx.x, lane = tid & 31, warp = tid >> 5;
    int wm = warp & 1, wn = warp >> 1, g = lane >> 2, tg = lane & 3;
    float acc[4][4][4] = {};
    uint4 ra[4], rb[4];
    const float* srcA = &g_V[h * KC_ * COLS_];
    const float* srcB = &g_QT[h * CHK * KC_];

    #define GC_LOAD(k0) {                                                      \
        _Pragma("unroll") for (int i = 0; i < 4; i++) {                        \
            int idx = tid + i * 256; int kk = idx >> 5, c = (idx & 31) * 4;    \
            ra[i] = *(const uint4*)&srcA[((k0) + kk) * COLS_ + col0 + c]; }    \
        _Pragma("unroll") for (int i = 0; i < 4; i++) {                        \
            int idx = tid + i * 256; int t = idx >> 3, k4 = (idx & 7) * 4;     \
            rb[i] = *(const uint4*)&srcB[t * KC_ + (k0) + k4]; } }
    #define GC_STORE() {                                                       \
        _Pragma("unroll") for (int i = 0; i < 4; i++) {                        \
            int idx = tid + i * 256; int kk = idx >> 5, c = (idx & 31) * 4;    \
            As[c * 36 + kk] = ra[i].x; As[(c + 1) * 36 + kk] = ra[i].y;        \
            As[(c + 2) * 36 + kk] = ra[i].z; As[(c + 3) * 36 + kk] = ra[i].w; }\
        _Pragma("unroll") for (int i = 0; i < 4; i++) {                        \
            int idx = tid + i * 256; int t = idx >> 3, k4 = (idx & 7) * 4;     \
            *(uint4*)&Bs[t * 36 + k4] = rb[i]; } }

    GC_LOAD(0); GC_STORE(); __syncthreads();
    for (int k0 = 0; k0 < KC_; k0 += 32) {
        bool more = (k0 + 32) < KC_;
        if (more) GC_LOAD(k0 + 32);
        GEMM_COMPUTE_PANEL(As, Bs, acc, wm, wn, g, tg);
        __syncthreads();
        if (more) { GC_STORE(); __syncthreads(); }
    }
    float* Gd = &g_G[h * COLS_ * CHK];
    #pragma unroll
    for (int mt = 0; mt < 4; mt++)
        #pragma unroll
        for (int nt = 0; nt < 4; nt++) {
            int r0 = col0 + wm * 64 + mt * 16 + g;   // col
            int c = wn * 32 + nt * 8 + 2 * tg;       // t
            *(float2*)&Gd[r0 * CHK + c] =
                make_float2(tf32f(gelu_f(acc[mt][nt][0])), tf32f(gelu_f(acc[mt][nt][1])));
            *(float2*)&Gd[(r0 + 8) * CHK + c] =
                make_float2(tf32f(gelu_f(acc[mt][nt][2])), tf32f(gelu_f(acc[mt][nt][3])));
        }
    #undef GC_LOAD
    #undef GC_STORE
}

// ---------------- GEMM-D: out[t][o] = sum_h G[h][col][t] * W1[o][h] + b1 + x ----------------
__global__ __launch_bounds__(256) void k_gemmD(const float* __restrict__ x,
                                               const float* __restrict__ W1,
                                               const float* __restrict__ b1,
                                               float* __restrict__ out) {
    __shared__ unsigned As[128 * 36], Bs[128 * 36];
    int col = blockIdx.x;                    // (b,c)
    int b = col >> 5, c = col & 31;
    int tid = threadIdx.x, lane = tid & 31, warp = tid >> 5;
    int wm = warp & 1, wn = warp >> 1, g = lane >> 2, tg = lane & 3;
    float acc[4][4][4] = {};
    uint4 ra[4], rb[4];

    #define GD_LOAD(h0) {                                                      \
        _Pragma("unroll") for (int i = 0; i < 4; i++) {                        \
            int idx = tid + i * 256; int kk = idx >> 5, t4 = (idx & 31) * 4;   \
            ra[i] = *(const uint4*)&g_G[(((h0) + kk) * COLS_ + col) * CHK + t4]; } \
        _Pragma("unroll") for (int i = 0; i < 4; i++) {                        \
            int idx = tid + i * 256; int o = idx >> 3, k4 = (idx & 7) * 4;     \
            float4 v = *(const float4*)&W1[o * H_ + (h0) + k4];                \
            rb[i].x = f2tf(v.x); rb[i].y = f2tf(v.y);                          \
            rb[i].z = f2tf(v.z); rb[i].w = f2tf(v.w); } }
    #define GD_STORE() {                                                       \
        _Pragma("unroll") for (int i = 0; i < 4; i++) {                        \
            int idx = tid + i * 256; int kk = idx >> 5, t4 = (idx & 31) * 4;   \
            As[t4 * 36 + kk] = ra[i].x; As[(t4 + 1) * 36 + kk] = ra[i].y;      \
            As[(t4 + 2) * 36 + kk] = ra[i].z; As[(t4 + 3) * 36 + kk] = ra[i].w; } \
        _Pragma("unroll") for (int i = 0; i < 4; i++) {                        \
            int idx = tid + i * 256; int o = idx >> 3, k4 = (idx & 7) * 4;     \
            *(uint4*)&Bs[o * 36 + k4] = rb[i]; } }

    GD_LOAD(0); GD_STORE(); __syncthreads();
    for (int h0 = 0; h0 < 128; h0 += 32) {
        bool more = (h0 + 32) < 128;
        if (more) GD_LOAD(h0 + 32);
        GEMM_COMPUTE_PANEL(As, Bs, acc, wm, wn, g, tg);
        __syncthreads();
        if (more) { GD_STORE(); __syncthreads(); }
    }
    #pragma unroll
    for (int mt = 0; mt < 4; mt++)
        #pragma unroll
        for (int nt = 0; nt < 4; nt++) {
            int t0 = wm * 64 + mt * 16 + g;
            int o  = wn * 32 + nt * 8 + 2 * tg;
            float2 bias = *(const float2*)&b1[o];
            size_t base0 = ((size_t)b * L_ + c * 128 + t0) * H_ + o;
            size_t base1 = ((size_t)b * L_ + c * 128 + t0 + 8) * H_ + o;
            float2 x0 = *(const float2*)&x[base0];
            float2 x1 = *(const float2*)&x[base1];
            *(float2*)&out[base0] = make_float2(acc[mt][nt][0] + bias.x + x0.x,
                                                acc[mt][nt][1] + bias.y + x0.y);
            *(float2*)&out[base1] = make_float2(acc[mt][nt][2] + bias.x + x1.x,
                                                acc[mt][nt][3] + bias.y + x1.y);
        }
    #undef GD_LOAD
    #undef GD_STORE
}

// ---------------- launch ----------------
extern "C" void kernel_launch(void* const* d_in, const int* in_sizes, int n_in,
                              void* d_out, int out_size) {
    const float* x     = (const float*)d_in[0];
    const float* Are   = (const float*)d_in[1];
    const float* Aim   = (const float*)d_in[2];
    const float* Bre   = (const float*)d_in[3];
    const float* Bim   = (const float*)d_in[4];
    const float* Cre   = (const float*)d_in[5];
    const float* Cim   = (const float*)d_in[6];
    const float* Dv    = (const float*)d_in[7];
    const float* logdt = (const float*)d_in[8];
    const float* W1    = (const float*)d_in[9];
    const float* b1    = (const float*)d_in[10];
    float* out = (float*)d_out;

    cudaFuncSetAttribute(k_gemmA, cudaFuncAttributeMaxDynamicSharedMemorySize, 128 * 133 * 4);

    k_pow<<<H_, 256>>>(Are, Aim, Bre, Bim, Cre, Cim, logdt);
    k_QT<<<H_, 192>>>(Dv);
    k_lnpart<<<dim3(B_, 32), 256>>>(x);
    k_lnfinal<<<B_, 32>>>();
    k_xpose<<<dim3(B_, CHK), 128>>>(x);
    k_gemmA<<<H_ * 4, 256, 128 * 133 * 4>>>();
    k_gemmC<<<H_ * 4, 256>>>();
    k_gemmD<<<COLS_, 256>>>(x, W1, b1, out);
}

// round 6
// speedup vs baseline: 2.3771x; 1.2323x over previous
#include <cuda_runtime.h>
#include <math.h>

// Problem dims
#define H_    128
#define B_    16
#define L_    4096
#define SN    64      // SSM state size N
#define CHK   128     // chunk length
#define NCH   32      // chunks (L/CHK)
#define COLS_ 512     // B_*NCH
#define KC_   256     // GEMM-C K dim (2*SN + CHK)

// ---------------- device scratch ----------------
static __device__ __align__(16) float g_wC [H_ * 128];         // [h][2n] w^128
static __device__ __align__(16) float g_WAT[H_ * 128 * 128];   // [h][m][j] tf32-rounded
static __device__ __align__(16) float g_QT [H_ * CHK * KC_];   // [h][t][k] tf32-rounded
static __device__ __align__(16) float g_U  [H_ * 128 * COLS_]; // [h][j][col] u, tf32-rounded
static __device__ __align__(16) float g_G  [H_ * COLS_ * CHK]; // [h][col][t] tf32
static __device__ double g_part[B_ * 32 * 2];

__device__ __forceinline__ float gelu_f(float v) {
    return 0.5f * v * (1.0f + erff(v * 0.70710678118654752f));
}
__device__ __forceinline__ unsigned f2tf(float f) {
    unsigned u; asm("cvt.rna.tf32.f32 %0, %1;" : "=r"(u) : "f"(f)); return u;
}
__device__ __forceinline__ float tf32f(float f) { return __uint_as_float(f2tf(f)); }

__device__ __forceinline__ void mma8(float* d, const unsigned* a, const unsigned* b) {
    asm volatile("mma.sync.aligned.m16n8k8.row.col.f32.tf32.tf32.f32 "
        "{%0,%1,%2,%3}, {%4,%5,%6,%7}, {%8,%9}, {%0,%1,%2,%3};"
        : "+f"(d[0]), "+f"(d[1]), "+f"(d[2]), "+f"(d[3])
        : "r"(a[0]), "r"(a[1]), "r"(a[2]), "r"(a[3]), "r"(b[0]), "r"(b[1]));
}

// ---------------- precompute: powers + WAT + K + QT, all in one kernel ----------------
__global__ __launch_bounds__(256) void k_powQT(
                      const float* __restrict__ Are, const float* __restrict__ Aim,
                      const float* __restrict__ Bre, const float* __restrict__ Bim,
                      const float* __restrict__ Cre, const float* __restrict__ Cim,
                      const float* __restrict__ logdt, const float* __restrict__ Dv) {
    int h = blockIdx.x, tid = threadIdx.x;   // 256 threads
    __shared__ float st[128 * 33];           // power tile [chan][i]
    __shared__ float scb[128];
    __shared__ float sKf[128];
    float pre = 0.f, pim = 0.f, wre = 0.f, wim = 0.f, cbre = 0.f, cbim = 0.f;
    if (tid < 64) {
        int n = tid, hn = h * SN + n;
        float dt = expf(logdt[h]);
        float are = Are[hn] * dt, aim = Aim[hn] * dt;
        float mag = expf(are);
        float s, c; sincosf(aim, &s, &c);
        wre = mag * c; wim = mag * s;        // w = exp(dt*A)
        cbre = (Cre[hn] * Bre[hn] - Cim[hn] * Bim[hn]) * dt;
        cbim = (Cre[hn] * Bim[hn] + Cim[hn] * Bre[hn]) * dt;
        scb[2 * n] = cbre; scb[2 * n + 1] = cbim;
        pre = 1.f; pim = 0.f;
    }
    __syncthreads();
    for (int l0 = 0; l0 < 128; l0 += 32) {
        if (tid < 64) {
            int n = tid;
            #pragma unroll 8
            for (int i = 0; i < 32; i++) {
                st[(2 * n) * 33 + i]     = pre;
                st[(2 * n + 1) * 33 + i] = pim;
                float nr = wre * pre - wim * pim;
                pim = wre * pim + wim * pre;
                pre = nr;
            }
        }
        __syncthreads();
        for (int idx = tid; idx < 4096; idx += 256) {
            int chan = idx >> 5, i = idx & 31;
            int m = (chan & 1) ? 64 + (chan >> 1) : (chan >> 1);
            g_WAT[(h * 128 + m) * 128 + 127 - (l0 + i)] = tf32f(st[chan * 33 + i]);
        }
        if (tid >= 64 && tid < 96) {
            int i = tid - 64;
            float a = 0.f;
            #pragma unroll 8
            for (int n = 0; n < 64; n++)
                a += scb[2 * n] * st[(2 * n) * 33 + i]
                   - scb[2 * n + 1] * st[(2 * n + 1) * 33 + i];
            sKf[l0 + i] = a;
        }
        __syncthreads();
    }
    if (tid < 64) {                          // state now = w^128
        g_wC[h * 128 + 2 * tid]     = pre;
        g_wC[h * 128 + 2 * tid + 1] = pim;
    }
    __syncthreads();
    // QT[h][t][k]: k<64 Re(CB*w^(t+1)); 64..127 -Im; k>=128 Toeplitz K
    if (tid < 64) {
        int n = tid;
        float qre = cbre * wre - cbim * wim; // CB * w^1
        float qim = cbre * wim + cbim * wre;
        for (int t = 0; t < CHK; t++) {
            g_QT[(h * CHK + t) * KC_ + n]      = tf32f(qre);
            g_QT[(h * CHK + t) * KC_ + 64 + n] = tf32f(-qim);
            float nr = qre * wre - qim * wim;
            qim = qre * wim + qim * wre;
            qre = nr;
        }
    } else if (tid < 192) {
        int j = tid - 64;                    // 0..127
        float K0D = sKf[0] + Dv[h];
        for (int t = 0; t < CHK; t++) {
            float v = (j < t) ? sKf[t - j] : (j == t ? K0D : 0.f);
            g_QT[(h * CHK + t) * KC_ + 128 + j] = tf32f(v);
        }
    }
}

// ---------------- LayerNorm partial sums over (L,H) per batch ----------------
__global__ __launch_bounds__(256) void k_lnpart(const float* __restrict__ x) {
    int b = blockIdx.x, s = blockIdx.y;      // 16 x 32
    const float4* p = (const float4*)(x + (size_t)b * (L_ * H_)) + (size_t)s * 4096;
    float su = 0.f, sq = 0.f;
    for (int i = threadIdx.x; i < 4096; i += 256) {
        float4 v = p[i];
        su += v.x + v.y + v.z + v.w;
        sq += v.x * v.x + v.y * v.y + v.z * v.z + v.w * v.w;
    }
    double ds = (double)su, dq = (double)sq;
    #pragma unroll
    for (int o = 16; o > 0; o >>= 1) {
        ds += __shfl_down_sync(0xffffffffu, ds, o);
        dq += __shfl_down_sync(0xffffffffu, dq, o);
    }
    __shared__ double ws[8], wq[8];
    int lane = threadIdx.x & 31, warp = threadIdx.x >> 5;
    if (lane == 0) { ws[warp] = ds; wq[warp] = dq; }
    __syncthreads();
    if (threadIdx.x == 0) {
        double S = 0, Q = 0;
        for (int i = 0; i < 8; i++) { S += ws[i]; Q += wq[i]; }
        g_part[(b * 32 + s) * 2]     = S;
        g_part[(b * 32 + s) * 2 + 1] = Q;
    }
}

// ---------------- normalize + transpose into g_U (tf32-rounded); LN-final folded in ----------------
__global__ __launch_bounds__(128) void k_xpose(const float* __restrict__ x) {
    int b = blockIdx.x, j = blockIdx.y;
    int tid = threadIdx.x;                   // 128
    __shared__ float sx[32 * 129];
    __shared__ float sms[2];
    if (tid < 32) {
        double s = g_part[(b * 32 + tid) * 2];
        double q = g_part[(b * 32 + tid) * 2 + 1];
        #pragma unroll
        for (int o = 16; o > 0; o >>= 1) {
            s += __shfl_down_sync(0xffffffffu, s, o);
            q += __shfl_down_sync(0xffffffffu, q, o);
        }
        if (tid == 0) {
            double inv = 1.0 / (double)(L_ * H_);
            double mean = s * inv;
            double var  = q * inv - mean * mean;
            sms[0] = (float)mean;
            sms[1] = (float)(1.0 / sqrt(var + 1e-5));
        }
    }
    #pragma unroll 4
    for (int c = 0; c < 32; c++)
        sx[c * 129 + tid] = x[((size_t)b * L_ + (size_t)c * 128 + j) * H_ + tid];
    __syncthreads();
    float mean = sms[0], rstd = sms[1];
    int w = tid >> 5, lane = tid & 31;
    for (int h0 = w; h0 < 128; h0 += 4)
        g_U[(h0 * 128 + j) * COLS_ + b * 32 + lane] =
            tf32f((sx[lane * 129 + h0] - mean) * rstd);
}

// ---------------- tf32 GEMM compute panel (A,B from smem, [row*36+k] layout) ----------------
#define GEMM_COMPUTE_PANEL(As, Bs, acc, wm, wn, g, tg)                         \
    _Pragma("unroll")                                                          \
    for (int ks = 0; ks < 32; ks += 8) {                                       \
        unsigned a[4][4], bf[4][2];                                            \
        _Pragma("unroll")                                                      \
        for (int mt = 0; mt < 4; mt++) {                                       \
            int r = (wm) * 64 + mt * 16 + (g);                                 \
            a[mt][0] = (As)[r * 36 + ks + (tg)];                               \
            a[mt][1] = (As)[(r + 8) * 36 + ks + (tg)];                         \
            a[mt][2] = (As)[r * 36 + ks + (tg) + 4];                           \
            a[mt][3] = (As)[(r + 8) * 36 + ks + (tg) + 4];                     \
        }                                                                      \
        _Pragma("unroll")                                                      \
        for (int nt = 0; nt < 4; nt++) {                                       \
            int nn = (wn) * 32 + nt * 8 + (g);                                 \
            bf[nt][0] = (Bs)[nn * 36 + ks + (tg)];                             \
            bf[nt][1] = (Bs)[nn * 36 + ks + (tg) + 4];                         \
        }                                                                      \
        _Pragma("unroll")                                                      \
        for (int mt = 0; mt < 4; mt++)                                         \
            _Pragma("unroll")                                                  \
            for (int nt = 0; nt < 4; nt++)                                     \
                mma8(acc[mt][nt], a[mt], bf[nt]);                              \
    }

// A operand from sP (element (row,k) at sP[k*136 + row]; values tf32-prerounded)
#define GEMM_PANEL_SP(k0, Bs, acc, wm, wn, g, tg)                              \
    _Pragma("unroll")                                                          \
    for (int ks = 0; ks < 32; ks += 8) {                                       \
        unsigned a[4][4], bf[4][2];                                            \
        _Pragma("unroll")                                                      \
        for (int mt = 0; mt < 4; mt++) {                                       \
            int r = (wm) * 64 + mt * 16 + (g);                                 \
            a[mt][0] = __float_as_uint(sP[((k0) + ks + (tg)) * 136 + r]);      \
            a[mt][1] = __float_as_uint(sP[((k0) + ks + (tg)) * 136 + r + 8]);  \
            a[mt][2] = __float_as_uint(sP[((k0) + ks + (tg) + 4) * 136 + r]);  \
            a[mt][3] = __float_as_uint(sP[((k0) + ks + (tg) + 4) * 136 + r + 8]);\
        }                                                                      \
        _Pragma("unroll")                                                      \
        for (int nt = 0; nt < 4; nt++) {                                       \
            int nn = (wn) * 32 + nt * 8 + (g);                                 \
            bf[nt][0] = (Bs)[nn * 36 + ks + (tg)];                             \
            bf[nt][1] = (Bs)[nn * 36 + ks + (tg) + 4];                         \
        }                                                                      \
        _Pragma("unroll")                                                      \
        for (int mt = 0; mt < 4; mt++)                                         \
            _Pragma("unroll")                                                  \
            for (int nt = 0; nt < 4; nt++)                                     \
                mma8(acc[mt][nt], a[mt], bf[nt]);                              \
    }

// ---------------- fused GEMM-A + prefix scan + GEMM-C ----------------
// Phase1: P[m][col] = sum_j WAT[m][j]*u[j][col]  (u panels persist in smem)
// Scan:   Sin state per chunk (in sP, tf32-rounded)
// Phase2: G[col][t] = gelu( sum_k [Sin;u](k,col) * QT[t][k] )
#define SMEM_ABC ((6 * 4608) * 4 + 128 * 136 * 4)
__global__ __launch_bounds__(256) void k_gemmABC() {
    extern __shared__ unsigned smem[];
    unsigned* Us = smem;                         // [4][4608] u panels [c*36+kk]
    unsigned* Ws = smem + 4 * 4608;              // [2][4608] double buffer
    float* sP = (float*)(smem + 6 * 4608);       // [128*136]
    int h = blockIdx.x >> 2, col0 = (blockIdx.x & 3) * 128;
    int tid = threadIdx.x, lane = tid & 31, warp = tid >> 5;
    int wm = warp & 1, wn = warp >> 1, g = lane >> 2, tg = lane & 3;
    const float* srcU = &g_U[h * 128 * COLS_];
    const float* srcW = &g_WAT[h * 128 * 128];
    const float* srcQ = &g_QT[h * CHK * KC_];

    // ---- load all 4 u panels into Us (persist whole kernel) ----
    {
        uint4 t0[4], t1[4];
        #pragma unroll
        for (int pp = 0; pp < 4; pp += 2) {
            #pragma unroll
            for (int i = 0; i < 4; i++) {
                int idx = tid + i * 256; int kk = idx >> 5, c = (idx & 31) * 4;
                t0[i] = *(const uint4*)&srcU[(pp * 32 + kk) * COLS_ + col0 + c];
                t1[i] = *(const uint4*)&srcU[((pp + 1) * 32 + kk) * COLS_ + col0 + c];
            }
            #pragma unroll
            for (int i = 0; i < 4; i++) {
                int idx = tid + i * 256; int kk = idx >> 5, c = (idx & 31) * 4;
                unsigned* U0 = Us + pp * 4608;
                unsigned* U1 = Us + (pp + 1) * 4608;
                U0[c * 36 + kk] = t0[i].x; U0[(c + 1) * 36 + kk] = t0[i].y;
                U0[(c + 2) * 36 + kk] = t0[i].z; U0[(c + 3) * 36 + kk] = t0[i].w;
                U1[c * 36 + kk] = t1[i].x; U1[(c + 1) * 36 + kk] = t1[i].y;
                U1[(c + 2) * 36 + kk] = t1[i].z; U1[(c + 3) * 36 + kk] = t1[i].w;
            }
        }
    }
    // WAT panel 0 into Ws[0]
    uint4 wa[4];
    #pragma unroll
    for (int i = 0; i < 4; i++) {
        int idx = tid + i * 256; int m = idx >> 3, k4 = (idx & 7) * 4;
        wa[i] = *(const uint4*)&srcW[m * 128 + k4];
    }
    #pragma unroll
    for (int i = 0; i < 4; i++) {
        int idx = tid + i * 256; int m = idx >> 3, k4 = (idx & 7) * 4;
        *(uint4*)&Ws[m * 36 + k4] = wa[i];
    }
    __syncthreads();

    float acc[4][4][4] = {};
    // ---- phase 1 mainloop ----
    for (int p = 0; p < 4; p++) {
        if (p < 3) {
            #pragma unroll
            for (int i = 0; i < 4; i++) {
                int idx = tid + i * 256; int m = idx >> 3, k4 = (idx & 7) * 4;
                wa[i] = *(const uint4*)&srcW[m * 128 + (p + 1) * 32 + k4];
            }
        }
        GEMM_COMPUTE_PANEL((Ws + (p & 1) * 4608), (Us + p * 4608), acc, wm, wn, g, tg);
        if (p < 3) {
            #pragma unroll
            for (int i = 0; i < 4; i++) {
                int idx = tid + i * 256; int m = idx >> 3, k4 = (idx & 7) * 4;
                *(uint4*)&Ws[((p + 1) & 1) * 4608 + m * 36 + k4] = wa[i];
            }
            __syncthreads();
        }
    }
    // ---- stage P into sP[m][col_local], stride 136 ----
    #pragma unroll
    for (int mt = 0; mt < 4; mt++)
        #pragma unroll
        for (int nt = 0; nt < 4; nt++) {
            int r0 = wm * 64 + mt * 16 + g;
            int cl = wn * 32 + nt * 8 + 2 * tg;
            sP[r0 * 136 + cl]           = acc[mt][nt][0];
            sP[r0 * 136 + cl + 1]       = acc[mt][nt][1];
            sP[(r0 + 8) * 136 + cl]     = acc[mt][nt][2];
            sP[(r0 + 8) * 136 + cl + 1] = acc[mt][nt][3];
        }
    __syncthreads();

    // ---- prefetch QT panel 0 into Ws[0] (phase-1 Ws reads all done) ----
    uint4 qb[4];
    #pragma unroll
    for (int i = 0; i < 4; i++) {
        int idx = tid + i * 256; int t = idx >> 3, k4 = (idx & 7) * 4;
        qb[i] = *(const uint4*)&srcQ[t * KC_ + k4];
    }
    #pragma unroll
    for (int i = 0; i < 4; i++) {
        int idx = tid + i * 256; int t = idx >> 3, k4 = (idx & 7) * 4;
        *(uint4*)&Ws[t * 36 + k4] = qb[i];
    }

    // ---- prefix scan over 32 chunks (overlapped with QT prefetch latency) ----
    {
        int n = tid & 63, bl = tid >> 6;
        float wre = g_wC[h * 128 + 2 * n], wim = g_wC[h * 128 + 2 * n + 1];
        float sre = 0.f, sim = 0.f;
        #pragma unroll 4
        for (int c = 0; c < 32; c++) {
            int colI = bl * 32 + c;
            float pr = sP[n * 136 + colI];
            float pi = sP[(64 + n) * 136 + colI];
            sP[n * 136 + colI]        = tf32f(sre);
            sP[(64 + n) * 136 + colI] = tf32f(sim);
            float nr = wre * sre - wim * sim + pr;
            sim = wre * sim + wim * sre + pi;
            sre = nr;
        }
    }
    __syncthreads();

    // ---- phase 2 mainloop ----
    #pragma unroll
    for (int mt = 0; mt < 4; mt++)
        #pragma unroll
        for (int nt = 0; nt < 4; nt++)
            #pragma unroll
            for (int q = 0; q < 4; q++) acc[mt][nt][q] = 0.f;
    for (int p = 0; p < 8; p++) {
        if (p < 7) {
            #pragma unroll
            for (int i = 0; i < 4; i++) {
                int idx = tid + i * 256; int t = idx >> 3, k4 = (idx & 7) * 4;
                qb[i] = *(const uint4*)&srcQ[t * KC_ + (p + 1) * 32 + k4];
            }
        }
        if (p < 4) {
            GEMM_PANEL_SP(p * 32, (Ws + (p & 1) * 4608), acc, wm, wn, g, tg);
        } else {
            GEMM_COMPUTE_PANEL((Us + (p - 4) * 4608), (Ws + (p & 1) * 4608), acc, wm, wn, g, tg);
        }
        if (p < 7) {
            #pragma unroll
            for (int i = 0; i < 4; i++) {
                int idx = tid + i * 256; int t = idx >> 3, k4 = (idx & 7) * 4;
                *(uint4*)&Ws[((p + 1) & 1) * 4608 + t * 36 + k4] = qb[i];
            }
            __syncthreads();
        }
    }
    // ---- epilogue: GELU, write G[h][col][t] ----
    float* Gd = &g_G[h * COLS_ * CHK];
    #pragma unroll
    for (int mt = 0; mt < 4; mt++)
        #pragma unroll
        for (int nt = 0; nt < 4; nt++) {
            int r0 = col0 + wm * 64 + mt * 16 + g;   // col
            int c = wn * 32 + nt * 8 + 2 * tg;       // t
            *(float2*)&Gd[r0 * CHK + c] =
                make_float2(tf32f(gelu_f(acc[mt][nt][0])), tf32f(gelu_f(acc[mt][nt][1])));
            *(float2*)&Gd[(r0 + 8) * CHK + c] =
                make_float2(tf32f(gelu_f(acc[mt][nt][2])), tf32f(gelu_f(acc[mt][nt][3])));
        }
}

// ---------------- GEMM-D: out[t][o] = sum_h G[h][col][t] * W1[o][h] + b1 + x ----------------
__global__ __launch_bounds__(256) void k_gemmD(const float* __restrict__ x,
                                               const float* __restrict__ W1,
                                               const float* __restrict__ b1,
                                               float* __restrict__ out) {
    __shared__ unsigned As[128 * 36], Bs[128 * 36];
    int col = blockIdx.x;                    // (b,c)
    int b = col >> 5, c = col & 31;
    int tid = threadIdx.x, lane = tid & 31, warp = tid >> 5;
    int wm = warp & 1, wn = warp >> 1, g = lane >> 2, tg = lane & 3;
    float acc[4][4][4] = {};
    uint4 ra[4], rb[4];

    #define GD_LOAD(h0) {                                                      \
        _Pragma("unroll") for (int i = 0; i < 4; i++) {                        \
            int idx = tid + i * 256; int kk = idx >> 5, t4 = (idx & 31) * 4;   \
            ra[i] = *(const uint4*)&g_G[(((h0) + kk) * COLS_ + col) * CHK + t4]; } \
        _Pragma("unroll") for (int i = 0; i < 4; i++) {                        \
            int idx = tid + i * 256; int o = idx >> 3, k4 = (idx & 7) * 4;     \
            float4 v = *(const float4*)&W1[o * H_ + (h0) + k4];                \
            rb[i].x = f2tf(v.x); rb[i].y = f2tf(v.y);                          \
            rb[i].z = f2tf(v.z); rb[i].w = f2tf(v.w); } }
    #define GD_STORE() {                                                       \
        _Pragma("unroll") for (int i = 0; i < 4; i++) {                        \
            int idx = tid + i * 256; int kk = idx >> 5, t4 = (idx & 31) * 4;   \
            As[t4 * 36 + kk] = ra[i].x; As[(t4 + 1) * 36 + kk] = ra[i].y;      \
            As[(t4 + 2) * 36 + kk] = ra[i].z; As[(t4 + 3) * 36 + kk] = ra[i].w; } \
        _Pragma("unroll") for (int i = 0; i < 4; i++) {                        \
            int idx = tid + i * 256; int o = idx >> 3, k4 = (idx & 7) * 4;     \
            *(uint4*)&Bs[o * 36 + k4] = rb[i]; } }

    GD_LOAD(0); GD_STORE(); __syncthreads();
    for (int h0 = 0; h0 < 128; h0 += 32) {
        bool more = (h0 + 32) < 128;
        if (more) GD_LOAD(h0 + 32);
        GEMM_COMPUTE_PANEL(As, Bs, acc, wm, wn, g, tg);
        __syncthreads();
        if (more) { GD_STORE(); __syncthreads(); }
    }
    #pragma unroll
    for (int mt = 0; mt < 4; mt++)
        #pragma unroll
        for (int nt = 0; nt < 4; nt++) {
            int t0 = wm * 64 + mt * 16 + g;
            int o  = wn * 32 + nt * 8 + 2 * tg;
            float2 bias = *(const float2*)&b1[o];
            size_t base0 = ((size_t)b * L_ + c * 128 + t0) * H_ + o;
            size_t base1 = ((size_t)b * L_ + c * 128 + t0 + 8) * H_ + o;
            float2 x0 = *(const float2*)&x[base0];
            float2 x1 = *(const float2*)&x[base1];
            *(float2*)&out[base0] = make_float2(acc[mt][nt][0] + bias.x + x0.x,
                                                acc[mt][nt][1] + bias.y + x0.y);
            *(float2*)&out[base1] = make_float2(acc[mt][nt][2] + bias.x + x1.x,
                                                acc[mt][nt][3] + bias.y + x1.y);
        }
    #undef GD_LOAD
    #undef GD_STORE
}

// ---------------- launch ----------------
extern "C" void kernel_launch(void* const* d_in, const int* in_sizes, int n_in,
                              void* d_out, int out_size) {
    const float* x     = (const float*)d_in[0];
    const float* Are   = (const float*)d_in[1];
    const float* Aim   = (const float*)d_in[2];
    const float* Bre   = (const float*)d_in[3];
    const float* Bim   = (const float*)d_in[4];
    const float* Cre   = (const float*)d_in[5];
    const float* Cim   = (const float*)d_in[6];
    const float* Dv    = (const float*)d_in[7];
    const float* logdt = (const float*)d_in[8];
    const float* W1    = (const float*)d_in[9];
    const float* b1    = (const float*)d_in[10];
    float* out = (float*)d_out;

    cudaFuncSetAttribute(k_gemmABC, cudaFuncAttributeMaxDynamicSharedMemorySize, SMEM_ABC);

    k_powQT<<<H_, 256>>>(Are, Aim, Bre, Bim, Cre, Cim, logdt, Dv);
    k_lnpart<<<dim3(B_, 32), 256>>>(x);
    k_xpose<<<dim3(B_, CHK), 128>>>(x);
    k_gemmABC<<<H_ * 4, 256, SMEM_ABC>>>();
    k_gemmD<<<COLS_, 256>>>(x, W1, b1, out);
}